// round 2
// baseline (speedup 1.0000x reference)
#include <cuda_runtime.h>

// Single-pass fused GAE reverse scan with decoupled lookback.
//   adv_t = delta_t + c_t * adv_{t+1},  c_t = GAMMA*LAMBDA*(1-done_{t+1})
//   delta_t = r_t + GAMMA*v_{t+1}*(1-done_{t+1}) - v_t   (v_T=0, done_T=1)
// Output: d_out[0:T*N] = advantages, d_out[T*N:2*T*N] = advantages + values.
//
// Decomposition: within a chunk of R rows, adv_t = adv0_t + carry * P_t where
// adv0_t = local scan with zero carry, P_t = prod_{s=t..hi} c_s, and carry is
// the advantage entering from the chunk above (later time). Per-chunk affine
// aggregate (A,B) = (adv0_lo, P_lo);  prefix(k) = A_k + B_k * prefix(k+1).

#define T_DIM   2048
#define N_DIM   4096
#define R       32                 // rows per chunk
#define CT      (T_DIM / R)        // 64 chunks in time
#define BLOCK   256                // threads = columns per block
#define CG      (N_DIM / BLOCK)    // 16 column groups

#define GAMMA_F 0.99f
#define GL_F    (0.99f * 0.95f)

#define FLAG_AGG    1
#define FLAG_PREFIX 2

// Scratch (__device__ globals; no allocation allowed): 3 MB + 4 KB.
__device__ float g_A   [CT * N_DIM];
__device__ float g_B   [CT * N_DIM];
__device__ float g_pref[CT * N_DIM];
__device__ int   g_flag[CT * CG];

__global__ __launch_bounds__(BLOCK)
void gae_fused(const float* __restrict__ rew,
               const float* __restrict__ val,
               const float* __restrict__ don,
               float* __restrict__ out)
{
    extern __shared__ float smem[];
    float* s_adv0 = smem;                    // [R * BLOCK]
    float* s_P    = smem + R * BLOCK;        // [R * BLOCK]
    float* s_v    = smem + 2 * R * BLOCK;    // [R * BLOCK]

    const int g   = blockIdx.x;              // column group
    const int L   = blockIdx.y;              // level: 0 = latest time chunk
    const int k   = CT - 1 - L;              // time chunk index
    const int tid = threadIdx.x;
    const int n   = g * BLOCK + tid;         // column
    const int lo  = k * R;
    const int hi  = lo + R - 1;

    // ---- Phase 1: load inputs once, local reverse scan with zero carry ----
    float v_next, d_next;
    if (k == CT - 1) {
        v_next = 0.0f;
        d_next = 1.0f;
    } else {
        v_next = val[(size_t)(hi + 1) * N_DIM + n];
        d_next = don[(size_t)(hi + 1) * N_DIM + n];
    }

    float A = 0.0f;   // running adv0 (scan with carry 0)
    float B = 1.0f;   // running suffix product of c

    #pragma unroll
    for (int i = R - 1; i >= 0; --i) {
        const size_t idx = (size_t)(lo + i) * N_DIM + n;
        const float rt = rew[idx];
        const float vt = val[idx];
        const float dt = don[idx];

        const float nt    = 1.0f - d_next;
        const float delta = fmaf(GAMMA_F * nt, v_next, rt) - vt;
        const float c     = GL_F * nt;

        A = fmaf(c, A, delta);
        B = c * B;

        s_adv0[i * BLOCK + tid] = A;
        s_P   [i * BLOCK + tid] = B;
        s_v   [i * BLOCK + tid] = vt;

        v_next = vt;
        d_next = dt;
    }

    // ---- Publish + lookback ----
    float carry;
    if (k == CT - 1) {
        carry = 0.0f;
        g_pref[(size_t)k * N_DIM + n] = A;    // prefix = A + B*0
        __threadfence();
        __syncthreads();
        if (tid == 0) {
            *(volatile int*)&g_flag[k * CG + g] = FLAG_PREFIX;
        }
    } else {
        // publish aggregate first so others can make progress
        g_A[(size_t)k * N_DIM + n] = A;
        g_B[(size_t)k * N_DIM + n] = B;
        __threadfence();
        __syncthreads();
        if (tid == 0) {
            *(volatile int*)&g_flag[k * CG + g] = FLAG_AGG;
        }

        // lookback toward later time: carry_in(k) = a + b * prefix(j)
        float a = 0.0f, b = 1.0f;
        int j = k + 1;
        for (;;) {
            int fl = *(volatile int*)&g_flag[j * CG + g];
            if (fl == 0) {
                __nanosleep(40);
                continue;
            }
            __threadfence();   // acquire: order data reads after flag read
            if (fl == FLAG_PREFIX) {
                carry = fmaf(b, g_pref[(size_t)j * N_DIM + n], a);
                break;
            }
            // aggregate: fold and move on
            const float Aj = g_A[(size_t)j * N_DIM + n];
            const float Bj = g_B[(size_t)j * N_DIM + n];
            a = fmaf(b, Aj, a);
            b = b * Bj;
            ++j;
            if (j == CT) { carry = a; break; }   // unreachable (last chunk publishes PREFIX)
        }

        // publish own inclusive prefix ASAP to unblock earlier-time chunks
        g_pref[(size_t)k * N_DIM + n] = fmaf(B, carry, A);
        __threadfence();
        __syncthreads();
        if (tid == 0) {
            *(volatile int*)&g_flag[k * CG + g] = FLAG_PREFIX;
        }
    }

    // ---- Phase 2: apply carry, emit advantages and returns ----
    float* __restrict__ out_adv = out;
    float* __restrict__ out_ret = out + (size_t)T_DIM * N_DIM;

    #pragma unroll
    for (int i = 0; i < R; ++i) {
        const size_t idx = (size_t)(lo + i) * N_DIM + n;
        const float adv = fmaf(carry, s_P[i * BLOCK + tid], s_adv0[i * BLOCK + tid]);
        out_adv[idx] = adv;
        out_ret[idx] = adv + s_v[i * BLOCK + tid];
    }
}

// ---------------------------------------------------------------------------
extern "C" void kernel_launch(void* const* d_in, const int* in_sizes, int n_in,
                              void* d_out, int out_size)
{
    const float* rew = (const float*)d_in[0];
    const float* val = (const float*)d_in[1];
    const float* don = (const float*)d_in[2];
    float* out = (float*)d_out;

    // flags must be zero at the start of every replay
    void* flag_ptr = nullptr;
    cudaGetSymbolAddress(&flag_ptr, g_flag);
    cudaMemsetAsync(flag_ptr, 0, CT * CG * sizeof(int));

    const int smem_bytes = 3 * R * BLOCK * sizeof(float);   // 96 KB
    static bool configured = false;
    if (!configured) {
        cudaFuncSetAttribute(gae_fused,
                             cudaFuncAttributeMaxDynamicSharedMemorySize,
                             smem_bytes);
        configured = true;
    }

    dim3 block(BLOCK);
    dim3 grid(CG, CT);   // linear bid = g + L*CG  -> level 0 (latest time) first
    gae_fused<<<grid, block, smem_bytes>>>(rew, val, don, out);
}

// round 3
// speedup vs baseline: 1.0994x; 1.0994x over previous
#include <cuda_runtime.h>

// GAE reverse scan, 3-pass chunked linear recurrence, float4-vectorized.
//   adv_t = delta_t + c_t * adv_{t+1},  c_t = GL*(1-done_{t+1})
//   delta_t = r_t + GAMMA*v_{t+1}*(1-done_{t+1}) - v_t   (v_T=0, done_T=1)
// Output: d_out[0:T*N] = advantages, d_out[T*N:2*T*N] = advantages + values.

#define T_DIM   2048
#define N_DIM   4096
#define CT      64                  // chunks in time
#define LCH     (T_DIM / CT)        // 32 rows per chunk
#define BLOCK   256
#define VEC     4
#define N4      (N_DIM / VEC)       // 1024 float4 columns
#define NGRP    (N4 / BLOCK)        // 4 column groups

#define GAMMA_F 0.99f
#define GL_F    (0.99f * 0.95f)

// Scratch: per-(chunk, column) affine aggregate (A,B) and carries. 3 MB.
__device__ float2 g_AB   [CT * N_DIM];
__device__ float  g_carry[CT * N_DIM];

// ---------------------------------------------------------------------------
// Pass 1: per-chunk affine reduction. adv_top = A + B * carry_in.
// ---------------------------------------------------------------------------
__global__ __launch_bounds__(BLOCK)
void gae_pass1(const float4* __restrict__ rew,
               const float4* __restrict__ val,
               const float4* __restrict__ don)
{
    const int c4 = blockIdx.x * BLOCK + threadIdx.x;  // float4 column
    const int k  = blockIdx.y;
    const int lo = k * LCH;
    const int hi = lo + LCH - 1;

    float vn[VEC], dn[VEC], A[VEC], B[VEC];

    if (k == CT - 1) {
        #pragma unroll
        for (int j = 0; j < VEC; ++j) { vn[j] = 0.0f; dn[j] = 1.0f; }
    } else {
        float4 v4 = val[(size_t)(hi + 1) * N4 + c4];
        float4 d4 = don[(size_t)(hi + 1) * N4 + c4];
        const float* vp = (const float*)&v4;
        const float* dp = (const float*)&d4;
        #pragma unroll
        for (int j = 0; j < VEC; ++j) { vn[j] = vp[j]; dn[j] = dp[j]; }
    }
    #pragma unroll
    for (int j = 0; j < VEC; ++j) { A[j] = 0.0f; B[j] = 1.0f; }

    #pragma unroll 4
    for (int t = hi; t >= lo; --t) {
        const size_t idx = (size_t)t * N4 + c4;
        float4 r4 = rew[idx];
        float4 v4 = val[idx];
        float4 d4 = don[idx];
        const float* rp = (const float*)&r4;
        const float* vp = (const float*)&v4;
        const float* dp = (const float*)&d4;

        #pragma unroll
        for (int j = 0; j < VEC; ++j) {
            const float nt    = 1.0f - dn[j];
            const float delta = fmaf(GAMMA_F * nt, vn[j], rp[j]) - vp[j];
            const float c     = GL_F * nt;
            A[j] = fmaf(c, A[j], delta);
            B[j] = c * B[j];
            vn[j] = vp[j];
            dn[j] = dp[j];
        }
    }

    const int nbase = c4 * VEC;
    #pragma unroll
    for (int j = 0; j < VEC; ++j)
        g_AB[(size_t)k * N_DIM + nbase + j] = make_float2(A[j], B[j]);
}

// ---------------------------------------------------------------------------
// Mid: per-column reverse fold over CT chunk aggregates -> carry per chunk.
// ---------------------------------------------------------------------------
__global__ __launch_bounds__(BLOCK)
void gae_mid()
{
    const int n = blockIdx.x * BLOCK + threadIdx.x;

    float carry = 0.0f;
    #pragma unroll
    for (int k = CT - 1; k >= 0; --k) {
        const size_t idx = (size_t)k * N_DIM + n;
        g_carry[idx] = carry;
        const float2 ab = g_AB[idx];
        carry = fmaf(ab.y, carry, ab.x);
    }
}

// ---------------------------------------------------------------------------
// Pass 2: re-scan each chunk seeded with its carry; emit adv & returns.
// ---------------------------------------------------------------------------
__global__ __launch_bounds__(BLOCK)
void gae_pass2(const float4* __restrict__ rew,
               const float4* __restrict__ val,
               const float4* __restrict__ don,
               float4* __restrict__ out)
{
    const int c4 = blockIdx.x * BLOCK + threadIdx.x;
    const int k  = blockIdx.y;
    const int lo = k * LCH;
    const int hi = lo + LCH - 1;

    float vn[VEC], dn[VEC], adv[VEC];

    if (k == CT - 1) {
        #pragma unroll
        for (int j = 0; j < VEC; ++j) { vn[j] = 0.0f; dn[j] = 1.0f; }
    } else {
        float4 v4 = val[(size_t)(hi + 1) * N4 + c4];
        float4 d4 = don[(size_t)(hi + 1) * N4 + c4];
        const float* vp = (const float*)&v4;
        const float* dp = (const float*)&d4;
        #pragma unroll
        for (int j = 0; j < VEC; ++j) { vn[j] = vp[j]; dn[j] = dp[j]; }
    }

    const int nbase = c4 * VEC;
    #pragma unroll
    for (int j = 0; j < VEC; ++j)
        adv[j] = g_carry[(size_t)k * N_DIM + nbase + j];

    float4* __restrict__ out_adv = out;
    float4* __restrict__ out_ret = out + (size_t)T_DIM * N4;

    #pragma unroll 4
    for (int t = hi; t >= lo; --t) {
        const size_t idx = (size_t)t * N4 + c4;
        float4 r4 = rew[idx];
        float4 v4 = val[idx];
        float4 d4 = don[idx];
        const float* rp = (const float*)&r4;
        const float* vp = (const float*)&v4;
        const float* dp = (const float*)&d4;

        float4 oa, orr;
        float* oap = (float*)&oa;
        float* orp = (float*)&orr;

        #pragma unroll
        for (int j = 0; j < VEC; ++j) {
            const float nt    = 1.0f - dn[j];
            const float delta = fmaf(GAMMA_F * nt, vn[j], rp[j]) - vp[j];
            const float c     = GL_F * nt;
            adv[j] = fmaf(c, adv[j], delta);
            oap[j] = adv[j];
            orp[j] = adv[j] + vp[j];
            vn[j] = vp[j];
            dn[j] = dp[j];
        }

        out_adv[idx] = oa;
        out_ret[idx] = orr;
    }
}

// ---------------------------------------------------------------------------
extern "C" void kernel_launch(void* const* d_in, const int* in_sizes, int n_in,
                              void* d_out, int out_size)
{
    const float4* rew = (const float4*)d_in[0];
    const float4* val = (const float4*)d_in[1];
    const float4* don = (const float4*)d_in[2];
    float4* out = (float4*)d_out;

    dim3 block(BLOCK);
    dim3 grid(NGRP, CT);          // 4 x 64 = 256 blocks, all resident

    gae_pass1<<<grid, block>>>(rew, val, don);
    gae_mid<<<N_DIM / BLOCK, block>>>();
    gae_pass2<<<grid, block>>>(rew, val, don, out);
}

// round 4
// speedup vs baseline: 1.3552x; 1.2326x over previous
#include <cuda_runtime.h>

// GAE reverse scan, 3-pass chunked linear recurrence, float2-vectorized.
//   adv_t = delta_t + c_t * adv_{t+1},  c_t = GL*(1-done_{t+1})
//   delta_t = r_t + GAMMA*v_{t+1}*(1-done_{t+1}) - v_t   (v_T=0, done_T=1)
// Output: d_out[0:T*N] = advantages, d_out[T*N:2*T*N] = advantages + values.

#define T_DIM   2048
#define N_DIM   4096
#define CT      64                  // chunks in time
#define LCH     (T_DIM / CT)        // 32 rows per chunk
#define BLOCK   256
#define N2      (N_DIM / 2)         // 2048 float2 columns
#define NGRP    (N2 / BLOCK)        // 8 column groups -> 512 blocks

#define GAMMA_F 0.99f
#define GL_F    (0.99f * 0.95f)

// Scratch: per-(chunk, column) affine aggregate (A,B) and carries. 3 MB.
__device__ float2 g_AB   [CT * N_DIM];
__device__ float  g_carry[CT * N_DIM];

// ---------------------------------------------------------------------------
// Pass 1: per-chunk affine reduction. adv_top = A + B * carry_in.
// ---------------------------------------------------------------------------
__global__ __launch_bounds__(BLOCK, 4)
void gae_pass1(const float2* __restrict__ rew,
               const float2* __restrict__ val,
               const float2* __restrict__ don)
{
    const int c2 = blockIdx.x * BLOCK + threadIdx.x;  // float2 column
    const int k  = blockIdx.y;
    const int lo = k * LCH;
    const int hi = lo + LCH - 1;

    float vnx, vny, dnx, dny;
    if (k == CT - 1) {
        vnx = 0.0f; vny = 0.0f; dnx = 1.0f; dny = 1.0f;
    } else {
        const float2 v2 = val[(size_t)(hi + 1) * N2 + c2];
        const float2 d2 = don[(size_t)(hi + 1) * N2 + c2];
        vnx = v2.x; vny = v2.y; dnx = d2.x; dny = d2.y;
    }

    float Ax = 0.0f, Ay = 0.0f, Bx = 1.0f, By = 1.0f;

    #pragma unroll
    for (int t = hi; t >= lo; --t) {
        const size_t idx = (size_t)t * N2 + c2;
        const float2 r2 = rew[idx];
        const float2 v2 = val[idx];
        const float2 d2 = don[idx];

        const float ntx = 1.0f - dnx;
        const float nty = 1.0f - dny;
        const float dex = fmaf(GAMMA_F * ntx, vnx, r2.x) - v2.x;
        const float dey = fmaf(GAMMA_F * nty, vny, r2.y) - v2.y;
        const float cx  = GL_F * ntx;
        const float cy  = GL_F * nty;

        Ax = fmaf(cx, Ax, dex);
        Ay = fmaf(cy, Ay, dey);
        Bx = cx * Bx;
        By = cy * By;

        vnx = v2.x; vny = v2.y; dnx = d2.x; dny = d2.y;
    }

    const int nbase = c2 * 2;
    g_AB[(size_t)k * N_DIM + nbase + 0] = make_float2(Ax, Bx);
    g_AB[(size_t)k * N_DIM + nbase + 1] = make_float2(Ay, By);
}

// ---------------------------------------------------------------------------
// Mid: per-column reverse fold over CT chunk aggregates -> carry per chunk.
// Loads are address-independent across k (only the FMA chain is serial).
// ---------------------------------------------------------------------------
__global__ __launch_bounds__(BLOCK)
void gae_mid()
{
    const int n = blockIdx.x * BLOCK + threadIdx.x;

    float carry = 0.0f;
    #pragma unroll
    for (int k = CT - 1; k >= 0; --k) {
        const size_t idx = (size_t)k * N_DIM + n;
        g_carry[idx] = carry;
        const float2 ab = g_AB[idx];
        carry = fmaf(ab.y, carry, ab.x);
    }
}

// ---------------------------------------------------------------------------
// Pass 2: re-scan each chunk seeded with its carry; emit adv & returns.
// ---------------------------------------------------------------------------
__global__ __launch_bounds__(BLOCK, 4)
void gae_pass2(const float2* __restrict__ rew,
               const float2* __restrict__ val,
               const float2* __restrict__ don,
               float2* __restrict__ out)
{
    const int c2 = blockIdx.x * BLOCK + threadIdx.x;
    const int k  = blockIdx.y;
    const int lo = k * LCH;
    const int hi = lo + LCH - 1;

    float vnx, vny, dnx, dny;
    if (k == CT - 1) {
        vnx = 0.0f; vny = 0.0f; dnx = 1.0f; dny = 1.0f;
    } else {
        const float2 v2 = val[(size_t)(hi + 1) * N2 + c2];
        const float2 d2 = don[(size_t)(hi + 1) * N2 + c2];
        vnx = v2.x; vny = v2.y; dnx = d2.x; dny = d2.y;
    }

    const int nbase = c2 * 2;
    float advx = g_carry[(size_t)k * N_DIM + nbase + 0];
    float advy = g_carry[(size_t)k * N_DIM + nbase + 1];

    float2* __restrict__ out_adv = out;
    float2* __restrict__ out_ret = out + (size_t)T_DIM * N2;

    #pragma unroll
    for (int t = hi; t >= lo; --t) {
        const size_t idx = (size_t)t * N2 + c2;
        const float2 r2 = rew[idx];
        const float2 v2 = val[idx];
        const float2 d2 = don[idx];

        const float ntx = 1.0f - dnx;
        const float nty = 1.0f - dny;
        const float dex = fmaf(GAMMA_F * ntx, vnx, r2.x) - v2.x;
        const float dey = fmaf(GAMMA_F * nty, vny, r2.y) - v2.y;
        const float cx  = GL_F * ntx;
        const float cy  = GL_F * nty;

        advx = fmaf(cx, advx, dex);
        advy = fmaf(cy, advy, dey);

        out_adv[idx] = make_float2(advx, advy);
        out_ret[idx] = make_float2(advx + v2.x, advy + v2.y);

        vnx = v2.x; vny = v2.y; dnx = d2.x; dny = d2.y;
    }
}

// ---------------------------------------------------------------------------
extern "C" void kernel_launch(void* const* d_in, const int* in_sizes, int n_in,
                              void* d_out, int out_size)
{
    const float2* rew = (const float2*)d_in[0];
    const float2* val = (const float2*)d_in[1];
    const float2* don = (const float2*)d_in[2];
    float2* out = (float2*)d_out;

    dim3 block(BLOCK);
    dim3 grid(NGRP, CT);          // 8 x 64 = 512 blocks

    gae_pass1<<<grid, block>>>(rew, val, don);
    gae_mid<<<N_DIM / BLOCK, block>>>();
    gae_pass2<<<grid, block>>>(rew, val, don, out);
}